// round 8
// baseline (speedup 1.0000x reference)
#include <cuda_runtime.h>
#include <cuda_bf16.h>
#include <float.h>

#define N_BINS 15
#define NUM_CLS 1000
#define NUM_SEG (NUM_CLS * N_BINS)   // 15000, divisible by 4

// Scratch: per-(class,bin) signed accumulation of (conf - acc).
// Zero-initialized at module load; the LAST block of each run re-zeroes it
// after consuming it, so every graph replay starts from zeros.
__device__ float g_seg[NUM_SEG];
__device__ unsigned int g_arrive;   // arrival ticket (reset by last block)

// One warp per row (proven R3 loop — ~82us, at bandwidth ceiling), with the
// reduction fused in via the threadFenceReduction pattern (saves the ~6.4us
// second launch). Dtype probe inlined: warps ballot on the high 32-bit words
// of the first 32 would-be int64 labels (one hot L2 line). int64 labels in
// [0,1000) have all-zero high words; int32 all-zero prob = (1/1000)^32.
__global__ __launch_bounds__(256)
void ecce_main_kernel(const float* __restrict__ logits,
                      const void* __restrict__ labels,
                      float* __restrict__ out,
                      int N, int C) {
    int warp = (blockIdx.x * blockDim.x + threadIdx.x) >> 5;
    int lane = threadIdx.x & 31;

    if (warp < N) {
        // ---- inline dtype probe (all warps agree; single hot line) ----
        int nprobe = min(32, N >> 1);
        int nz = 0;
        if (lane < nprobe) nz = ((const int*)labels)[2 * lane + 1];
        unsigned any = __ballot_sync(0xFFFFFFFFu, nz != 0);
        bool lab64 = (any == 0);

        // Hoist the label load: overlaps the row loads below.
        int lab = 0;
        if (lane == 0) {
            if (lab64) lab = (int)((const long long*)labels)[warp];
            else       lab = ((const int*)labels)[warp];
            lab = min(max(lab, 0), NUM_CLS - 1);  // defensive
        }

        const float4* row = reinterpret_cast<const float4*>(logits + (size_t)warp * C);
        const int nvec = C >> 2;

        float m = -FLT_MAX;
        float s = 0.0f;
        int   idx = 0x7FFFFFFF;

        if (nvec == 250) {
            // ---- specialized C=1000 path: front-batch 8x LDG.128 per lane ----
            const float4 pad = make_float4(-FLT_MAX, -FLT_MAX, -FLT_MAX, -FLT_MAX);
            float4 v[8];
            #pragma unroll
            for (int k = 0; k < 8; k++) {
                int i = lane + (k << 5);
                v[k] = (i < 250) ? row[i] : pad;
            }
            // Phase A: local max + argmax (first occurrence; per-lane indices increase).
            #pragma unroll
            for (int k = 0; k < 8; k++) {
                int base = (lane + (k << 5)) << 2;
                #pragma unroll
                for (int e = 0; e < 4; e++) {
                    float x = (e == 0) ? v[k].x : (e == 1) ? v[k].y : (e == 2) ? v[k].z : v[k].w;
                    if (x > m) { m = x; idx = base + e; }
                }
            }
            // Phase B: un-rescaled exp-sum vs lane-local max (pads -> exp(-inf)=0).
            #pragma unroll
            for (int k = 0; k < 8; k++) {
                s += __expf(v[k].x - m) + __expf(v[k].y - m)
                   + __expf(v[k].z - m) + __expf(v[k].w - m);
            }
        } else {
            // ---- generic fallback (online softmax) ----
            for (int i = lane; i < nvec; i += 32) {
                float4 v = row[i];
                int base = i << 2;
                #pragma unroll
                for (int e = 0; e < 4; e++) {
                    float x = (e == 0) ? v.x : (e == 1) ? v.y : (e == 2) ? v.z : v.w;
                    int j = base + e;
                    if (x > m) {
                        s = s * __expf(m - x) + 1.0f;
                        m = x; idx = j;
                    } else {
                        s += __expf(x - m);
                    }
                }
            }
        }

        // Warp merge of (m, idx, s); tie-break toward lower index.
        #pragma unroll
        for (int off = 16; off > 0; off >>= 1) {
            float m2 = __shfl_down_sync(0xFFFFFFFFu, m, off);
            float s2 = __shfl_down_sync(0xFFFFFFFFu, s, off);
            int   i2 = __shfl_down_sync(0xFFFFFFFFu, idx, off);
            if (m2 > m || (m2 == m && i2 < idx)) {
                s = s * __expf(m - m2) + s2;
                m = m2; idx = i2;
            } else {
                s += s2 * __expf(m2 - m);
            }
        }

        if (lane == 0) {
            float conf = 1.0f / s;  // = exp(0)/sum(exp(l - max))
            int bin = (int)ceilf(conf * (float)N_BINS) - 1;
            bin = min(max(bin, 0), N_BINS - 1);
            float acc = (idx == lab) ? 1.0f : 0.0f;
            atomicAdd(&g_seg[lab * N_BINS + bin], conf - acc);
        }
    }

    // ---- fused last-block reduction (threadFenceReduction pattern) ----
    __syncthreads();                       // block-scope order of the atomics
    __shared__ unsigned int s_is_last;
    if (threadIdx.x == 0) {
        __threadfence();                   // publish this block's g_seg atomics
        unsigned int ticket = atomicAdd(&g_arrive, 1u);
        s_is_last = (ticket == gridDim.x - 1) ? 1u : 0u;
    }
    __syncthreads();
    if (!s_is_last) return;

    __threadfence();                       // acquire all blocks' g_seg writes

    // Vectorized tail: 3750 float4 across 256 threads (~15/thread, MLP-rich).
    __shared__ float sh[8];
    float4* p = reinterpret_cast<float4*>(g_seg);
    const float4 zero4 = make_float4(0.f, 0.f, 0.f, 0.f);
    float acc = 0.0f;
    #pragma unroll 4
    for (int i = threadIdx.x; i < NUM_SEG / 4; i += 256) {
        float4 v = p[i];
        acc += fabsf(v.x) + fabsf(v.y) + fabsf(v.z) + fabsf(v.w);
        p[i] = zero4;                      // restore zero invariant
    }
    #pragma unroll
    for (int off = 16; off > 0; off >>= 1)
        acc += __shfl_xor_sync(0xFFFFFFFFu, acc, off);
    int wid = threadIdx.x >> 5;
    if (lane == 0) sh[wid] = acc;
    __syncthreads();
    if (threadIdx.x == 0) {
        float t = 0.0f;
        #pragma unroll
        for (int w = 0; w < 8; w++) t += sh[w];
        out[0] = t / (float)N;
        g_arrive = 0u;                     // restore ticket for next replay
    }
}

extern "C" void kernel_launch(void* const* d_in, const int* in_sizes, int n_in,
                              void* d_out, int out_size) {
    // Logits is the (much) larger input; don't assume ordering.
    int i_logits = (in_sizes[0] >= in_sizes[1]) ? 0 : 1;
    int i_labels = 1 - i_logits;

    const float* logits = (const float*)d_in[i_logits];
    const void*  labels = d_in[i_labels];
    float*       out    = (float*)d_out;

    int N = in_sizes[i_labels];           // 131072
    int C = in_sizes[i_logits] / N;       // 1000

    int warps_per_block = 256 / 32;       // 8 rows per block
    int blocks = (N + warps_per_block - 1) / warps_per_block;
    ecce_main_kernel<<<blocks, 256>>>(logits, labels, out, N, C);
}